// round 1
// baseline (speedup 1.0000x reference)
#include <cuda_runtime.h>
#include <cstddef>

// ---------------- problem constants ----------------
#define RES7 7
constexpr int NBOX  = 1024;
constexpr int C_IN  = 128;
constexpr int REP   = 896;                 // 128 * 7
constexpr int MROWS = NBOX * RES7 * RES7;  // 50176
constexpr int KCONV = C_IN * RES7;         // 896
constexpr int INSZ  = REP * RES7 * RES7;   // 43904
constexpr int DIMX = 80, DIMY = 80, DIMZ = 20;
constexpr float PX_SCALE = 20.0f * 0.25f;  // VOXEL_SCALE * POOLER_SCALE = 5.0

// ---------------- scratch (static, no allocations) ----------------
constexpr size_t OFF_A     = 0;
constexpr size_t OFF_Y     = OFF_A  + (size_t)MROWS * KCONV;   // conv output
constexpr size_t OFF_X2    = OFF_Y  + (size_t)MROWS * REP;     // normalized, [N, 43904]
constexpr size_t OFF_H6    = OFF_X2 + (size_t)NBOX * INSZ;     // fc6 split-K acc
constexpr size_t OFF_X3    = OFF_H6 + (size_t)NBOX * REP;      // relu(fc6)
constexpr size_t OFF_H7    = OFF_X3 + (size_t)NBOX * REP;      // fc7 split-K acc
constexpr size_t OFF_STATS = OFF_H7 + (size_t)NBOX * REP;      // [2*896] sum / sumsq
constexpr size_t OFF_MEAN  = OFF_STATS + 2 * REP;
constexpr size_t OFF_RSIG  = OFF_MEAN + REP;
constexpr size_t SC_TOTAL  = OFF_RSIG + REP;

__device__ float g_scratch[SC_TOTAL];

// ---------------- zero init (stats + split-K accumulators) ----------------
__global__ void k_zero(float* __restrict__ h6, float* __restrict__ h7,
                       float* __restrict__ stats) {
    int i = blockIdx.x * blockDim.x + threadIdx.x;
    if (i < NBOX * REP) { h6[i] = 0.f; h7[i] = 0.f; }
    if (i < 2 * REP)    stats[i] = 0.f;
}

// ---------------- 3D ROIAlign -> A[50176, 896], k = c*7 + z ----------------
__global__ void k_roi(const float* __restrict__ feat,
                      const float* __restrict__ boxes,
                      const int*   __restrict__ bidx,
                      float* __restrict__ A) {
    const int xy = blockIdx.x;        // 0..48
    const int n  = blockIdx.y;        // 0..1023
    const int c  = threadIdx.x;       // 0..127
    const int qx = xy / RES7, qy = xy % RES7;

    const float x1 = boxes[n*6+0] * PX_SCALE, y1 = boxes[n*6+1] * PX_SCALE,
                z1 = boxes[n*6+2] * PX_SCALE, x2 = boxes[n*6+3] * PX_SCALE,
                y2 = boxes[n*6+4] * PX_SCALE, z2 = boxes[n*6+5] * PX_SCALE;
    const float bx = fmaxf(x2 - x1, 1.0f) * (1.0f / RES7);
    const float by = fmaxf(y2 - y1, 1.0f) * (1.0f / RES7);
    const float bz = fmaxf(z2 - z1, 1.0f) * (1.0f / RES7);

    const float px = x1 + ((float)qx + 0.5f) * bx;
    const float py = y1 + ((float)qy + 0.5f) * by;

    const float fx = floorf(px); const float lx = px - fx;
    const float fy = floorf(py); const float ly = py - fy;
    int ix0 = min(max((int)fx, 0), DIMX - 1);
    int ix1 = min(max((int)fx + 1, 0), DIMX - 1);
    int iy0 = min(max((int)fy, 0), DIMY - 1);
    int iy1 = min(max((int)fy + 1, 0), DIMY - 1);

    const int b = bidx[n];
    int   base[4];
    float wxy[4];
    base[0] = ((b*DIMX + ix0)*DIMY + iy0)*DIMZ; wxy[0] = (1.f-lx)*(1.f-ly);
    base[1] = ((b*DIMX + ix0)*DIMY + iy1)*DIMZ; wxy[1] = (1.f-lx)*ly;
    base[2] = ((b*DIMX + ix1)*DIMY + iy0)*DIMZ; wxy[2] = lx*(1.f-ly);
    base[3] = ((b*DIMX + ix1)*DIMY + iy1)*DIMZ; wxy[3] = lx*ly;

    float* Arow = A + (size_t)(n * 49 + xy) * KCONV;

    #pragma unroll
    for (int z = 0; z < RES7; z++) {
        const float pz = z1 + ((float)z + 0.5f) * bz;
        const float fz = floorf(pz); const float lz = pz - fz;
        int iz0 = min(max((int)fz, 0), DIMZ - 1);
        int iz1 = min(max((int)fz + 1, 0), DIMZ - 1);
        float v = 0.f;
        #pragma unroll
        for (int q = 0; q < 4; q++) {
            const float f0 = feat[(size_t)(base[q] + iz0) * C_IN + c];
            const float f1 = feat[(size_t)(base[q] + iz1) * C_IN + c];
            v += wxy[q] * ((1.f - lz) * f0 + lz * f1);
        }
        Arow[c * RES7 + z] = v;
    }
}

// ---------------- GEMM: 128x128x16 tiles, 8x8 microtile, 256 threads -------
// A: [M, lda] row-major (K-contig). B: BKN ? [K, ldb] (N-contig) : [N, ldb] (K-contig).
// EPI: 0 plain store, 1 store + column sum/sumsq atomics, 2 atomicAdd (split-K).
template<int BM, int BN, int BK, int TM, int TN, bool BKN, int EPI>
__global__ __launch_bounds__(256)
void k_gemm(const float* __restrict__ A, const float* __restrict__ B,
            float* __restrict__ C, int lda, int ldb, int ldc,
            int kChunk, float* __restrict__ stats) {
    static_assert(BM == 128 && BN == 128 && BK == 16 && TM == 8 && TN == 8, "cfg");
    __shared__ float As[BK][BM];
    __shared__ float Bs[BK][BN];

    const int tid   = threadIdx.x;
    const int nBase = blockIdx.x * BN;
    const int mBase = blockIdx.y * BM;
    const int k0    = blockIdx.z * kChunk;

    const int tnIdx = tid % (BN / TN);     // 0..15
    const int tmIdx = tid / (BN / TN);     // 0..15
    const int row0  = tmIdx * TM;
    const int col0  = tnIdx * TN;

    float acc[TM][TN];
    #pragma unroll
    for (int i = 0; i < TM; i++)
        #pragma unroll
        for (int j = 0; j < TN; j++) acc[i][j] = 0.f;

    for (int kt = 0; kt < kChunk; kt += BK) {
        // A tile (BMxBK), transpose into As[k][m]
        #pragma unroll
        for (int p = 0; p < 2; p++) {
            int id = tid + p * 256;
            int r  = id >> 2;
            int kq = (id & 3) * 4;
            float4 v = *(const float4*)&A[(size_t)(mBase + r) * lda + k0 + kt + kq];
            As[kq+0][r] = v.x; As[kq+1][r] = v.y; As[kq+2][r] = v.z; As[kq+3][r] = v.w;
        }
        if (BKN) { // B [K, N]: direct copy
            #pragma unroll
            for (int p = 0; p < 2; p++) {
                int id = tid + p * 256;
                int kr = id >> 5;
                int nq = (id & 31) * 4;
                *(float4*)&Bs[kr][nq] =
                    *(const float4*)&B[(size_t)(k0 + kt + kr) * ldb + nBase + nq];
            }
        } else {   // B [N, K]: transpose into Bs[k][n]
            #pragma unroll
            for (int p = 0; p < 2; p++) {
                int id = tid + p * 256;
                int r  = id >> 2;
                int kq = (id & 3) * 4;
                float4 v = *(const float4*)&B[(size_t)(nBase + r) * ldb + k0 + kt + kq];
                Bs[kq+0][r] = v.x; Bs[kq+1][r] = v.y; Bs[kq+2][r] = v.z; Bs[kq+3][r] = v.w;
            }
        }
        __syncthreads();

        #pragma unroll
        for (int kk = 0; kk < BK; kk++) {
            float a[TM], b[TN];
            *(float4*)&a[0] = *(const float4*)&As[kk][row0];
            *(float4*)&a[4] = *(const float4*)&As[kk][row0 + 4];
            *(float4*)&b[0] = *(const float4*)&Bs[kk][col0];
            *(float4*)&b[4] = *(const float4*)&Bs[kk][col0 + 4];
            #pragma unroll
            for (int i = 0; i < TM; i++)
                #pragma unroll
                for (int j = 0; j < TN; j++)
                    acc[i][j] = fmaf(a[i], b[j], acc[i][j]);
        }
        __syncthreads();
    }

    if (EPI == 2) {
        #pragma unroll
        for (int i = 0; i < TM; i++) {
            const size_t mo = (size_t)(mBase + row0 + i) * ldc + nBase + col0;
            #pragma unroll
            for (int j = 0; j < TN; j++) atomicAdd(&C[mo + j], acc[i][j]);
        }
    } else {
        #pragma unroll
        for (int i = 0; i < TM; i++) {
            const size_t mo = (size_t)(mBase + row0 + i) * ldc + nBase + col0;
            #pragma unroll
            for (int j = 0; j < TN; j += 4) {
                float4 v = make_float4(acc[i][j], acc[i][j+1], acc[i][j+2], acc[i][j+3]);
                *(float4*)&C[mo + j] = v;
            }
        }
    }

    if constexpr (EPI == 1) {  // fused per-column sum / sumsq for the norm
        __shared__ float sSum[BN];
        __shared__ float sSq[BN];
        for (int x = tid; x < BN; x += 256) { sSum[x] = 0.f; sSq[x] = 0.f; }
        __syncthreads();
        #pragma unroll
        for (int j = 0; j < TN; j++) {
            float s = 0.f, q = 0.f;
            #pragma unroll
            for (int i = 0; i < TM; i++) { s += acc[i][j]; q += acc[i][j] * acc[i][j]; }
            atomicAdd(&sSum[col0 + j], s);
            atomicAdd(&sSq [col0 + j], q);
        }
        __syncthreads();
        for (int x = tid; x < BN; x += 256) {
            atomicAdd(&stats[nBase + x],        sSum[x]);
            atomicAdd(&stats[REP + nBase + x],  sSq[x]);
        }
    }
}

// ---------------- finalize stats ----------------
__global__ void k_finalize(const float* __restrict__ stats,
                           float* __restrict__ mean, float* __restrict__ rsig) {
    int r = blockIdx.x * blockDim.x + threadIdx.x;
    if (r < REP) {
        const float inv = 1.0f / (float)MROWS;
        float mu = stats[r] * inv;
        float v  = stats[REP + r] * inv - mu * mu;
        mean[r] = mu;
        rsig[r] = rsqrtf(v + 1e-5f);
    }
}

// ---------- normalize + relu + transpose: Y[n*49+xy, r] -> X2[n, r*49+xy] ----
__global__ __launch_bounds__(256) void k_norm(
    const float* __restrict__ Y, float* __restrict__ X2,
    const float* __restrict__ mean, const float* __restrict__ rsig,
    const float* __restrict__ gamma, const float* __restrict__ beta) {
    const int n = blockIdx.x;
    __shared__ float tile[49][129];
    __shared__ float sm[128], sr[128], sg[128], sb[128];

    for (int rc = 0; rc < 7; rc++) {
        const int rbase = rc * 128;
        if (threadIdx.x < 128) {
            int r = rbase + threadIdx.x;
            sm[threadIdx.x] = mean[r];  sr[threadIdx.x] = rsig[r];
            sg[threadIdx.x] = gamma[r]; sb[threadIdx.x] = beta[r];
        }
        for (int idx = threadIdx.x; idx < 49 * 128; idx += 256) {
            int xy = idx >> 7, rr = idx & 127;
            tile[xy][rr] = Y[(size_t)(n * 49 + xy) * REP + rbase + rr];
        }
        __syncthreads();
        for (int o = threadIdx.x; o < 128 * 49; o += 256) {
            int rr = o / 49, xy = o % 49;
            float v = (tile[xy][rr] - sm[rr]) * sr[rr] * sg[rr] + sb[rr];
            X2[(size_t)n * INSZ + rbase * 49 + o] = fmaxf(v, 0.f);
        }
        __syncthreads();
    }
}

// ---------------- bias + relu ----------------
__global__ void k_bias_relu(const float* __restrict__ in,
                            const float* __restrict__ bias,
                            float* __restrict__ out) {
    int i = blockIdx.x * blockDim.x + threadIdx.x;
    if (i < NBOX * REP) {
        int col = i % REP;
        out[i] = fmaxf(in[i] + bias[col], 0.f);
    }
}

// ---------------- launch ----------------
extern "C" void kernel_launch(void* const* d_in, const int* in_sizes, int n_in,
                              void* d_out, int out_size) {
    const float* feat   = (const float*)d_in[0];
    const float* boxes  = (const float*)d_in[1];
    const float* conv_w = (const float*)d_in[2];
    // conv_b (d_in[3]) cancels exactly in the mean subtraction -> skipped
    const float* gamma  = (const float*)d_in[4];
    const float* beta   = (const float*)d_in[5];
    const float* fc6_w  = (const float*)d_in[6];
    const float* fc6_b  = (const float*)d_in[7];
    const float* fc7_w  = (const float*)d_in[8];
    const float* fc7_b  = (const float*)d_in[9];
    const int*   bidx   = (const int*)d_in[10];
    float* out = (float*)d_out;

    float* sc = nullptr;
    cudaGetSymbolAddress((void**)&sc, g_scratch);
    float* A     = sc + OFF_A;
    float* Y     = sc + OFF_Y;
    float* X2    = sc + OFF_X2;
    float* H6    = sc + OFF_H6;
    float* X3    = sc + OFF_X3;
    float* H7    = sc + OFF_H7;
    float* STATS = sc + OFF_STATS;
    float* MEAN  = sc + OFF_MEAN;
    float* RSIG  = sc + OFF_RSIG;

    // 1. zero split-K accumulators + stats
    k_zero<<<3584, 256>>>(H6, H7, STATS);
    // 2. ROIAlign -> A [50176, 896]
    k_roi<<<dim3(49, NBOX), 128>>>(feat, boxes, bidx, A);
    // 3. conv einsum GEMM (NT) + fused norm-stats epilogue
    k_gemm<128,128,16,8,8,false,1><<<dim3(7, 392, 1), 256>>>(
        A, conv_w, Y, KCONV, KCONV, REP, KCONV, STATS);
    // 4. mean / rsqrt(var)
    k_finalize<<<7, 128>>>(STATS, MEAN, RSIG);
    // 5. normalize + relu + transpose -> X2 [1024, 43904]
    k_norm<<<NBOX, 256>>>(Y, X2, MEAN, RSIG, gamma, beta);
    // 6. fc6 GEMM (NN, split-K 8 with atomic accumulation)
    k_gemm<128,128,16,8,8,true,2><<<dim3(7, 8, 8), 256>>>(
        X2, fc6_w, H6, INSZ, REP, REP, INSZ / 8, nullptr);
    k_bias_relu<<<3584, 256>>>(H6, fc6_b, X3);
    // 7. fc7 GEMM (NN, split-K 4)
    k_gemm<128,128,16,8,8,true,2><<<dim3(7, 8, 4), 256>>>(
        X3, fc7_w, H7, REP, REP, REP, REP / 4, nullptr);
    k_bias_relu<<<3584, 256>>>(H7, fc7_b, out);
}

// round 3
// speedup vs baseline: 2.0396x; 2.0396x over previous
#include <cuda_runtime.h>
#include <cuda_bf16.h>
#include <cstdint>
#include <cstddef>

// ---------------- problem constants ----------------
constexpr int RES7  = 7;
constexpr int NBOX  = 1024;
constexpr int C_IN  = 128;
constexpr int REP   = 896;                  // 128*7
constexpr int MROWS = NBOX * 49;            // 50176
constexpr int KCONV = 896;                  // C_IN*7
constexpr int INSZ  = 43904;                // REP*49
constexpr int DIMX = 80, DIMY = 80, DIMZ = 20;
constexpr float PX_SCALE = 5.0f;            // 20 * 0.25

// ---------------- static scratch ----------------
__device__ float          g_Y   [(size_t)MROWS * REP];
__device__ __nv_bfloat16  g_Ahi [(size_t)MROWS * KCONV];
__device__ __nv_bfloat16  g_Alo [(size_t)MROWS * KCONV];
__device__ __nv_bfloat16  g_X2hi[(size_t)NBOX * INSZ];
__device__ __nv_bfloat16  g_X2lo[(size_t)NBOX * INSZ];
__device__ __nv_bfloat16  g_W6Thi[(size_t)REP * INSZ];
__device__ __nv_bfloat16  g_W6Tlo[(size_t)REP * INSZ];
__device__ __nv_bfloat16  g_WChi[(size_t)REP * KCONV];
__device__ __nv_bfloat16  g_WClo[(size_t)REP * KCONV];
__device__ __nv_bfloat16  g_W7Thi[(size_t)REP * REP];
__device__ __nv_bfloat16  g_W7Tlo[(size_t)REP * REP];
__device__ __nv_bfloat16  g_X3hi[(size_t)NBOX * REP];
__device__ __nv_bfloat16  g_X3lo[(size_t)NBOX * REP];
__device__ float          g_H6  [(size_t)NBOX * REP];
__device__ float          g_H7  [(size_t)NBOX * REP];
__device__ float          g_stats[2 * REP];
__device__ float          g_mean[REP];
__device__ float          g_rsig[REP];

// ---------------- helpers ----------------
__device__ __forceinline__ uint32_t smem_u32(const void* p) {
    uint32_t a;
    asm("{ .reg .u64 t; cvta.to.shared.u64 t, %1; cvt.u32.u64 %0, t; }" : "=r"(a) : "l"(p));
    return a;
}
__device__ __forceinline__ void cp_async16(uint32_t dst, const void* src) {
    asm volatile("cp.async.cg.shared.global [%0], [%1], 16;" :: "r"(dst), "l"(src) : "memory");
}
#define CP_COMMIT() asm volatile("cp.async.commit_group;" ::: "memory")
#define CP_WAIT2()  asm volatile("cp.async.wait_group 2;" ::: "memory")

#define MMA16816(c, a, b)                                                   \
    asm volatile("mma.sync.aligned.m16n8k16.row.col.f32.bf16.bf16.f32 "     \
        "{%0,%1,%2,%3},{%4,%5,%6,%7},{%8,%9},{%0,%1,%2,%3};"                \
        : "+f"((c)[0]), "+f"((c)[1]), "+f"((c)[2]), "+f"((c)[3])            \
        : "r"((a)[0]), "r"((a)[1]), "r"((a)[2]), "r"((a)[3]),               \
          "r"((b)[0]), "r"((b)[1]))

__device__ __forceinline__ void split_bf16(float v, __nv_bfloat16& hi, __nv_bfloat16& lo) {
    hi = __float2bfloat16(v);
    lo = __float2bfloat16(v - __bfloat162float(hi));
}

// ================= mma.sync GEMM =================
// D[m,n] = sum_k A[m,k]*B[n,k]; A,B split (hi,lo) bf16, 3-term product.
// CTA 128x128, 8 warps (2x4), warp tile 64x32, BK=32, 3-stage cp.async pipe.
// EPI: 0 = plain fp32 store, 1 = atomicAdd fp32 (split-K).
constexpr int BK        = 32;
constexpr int STRIDE_W  = 20;                 // 32-bit words per smem row (80B, conflict-free)
constexpr int TILE_W    = 128 * STRIDE_W;     // words per tile
constexpr int STAGE_W   = 4 * TILE_W;         // Ahi,Alo,Bhi,Blo
constexpr int NSTAGE    = 3;
constexpr int GEMM_SMEM = NSTAGE * STAGE_W * 4;   // 122880 B

template<int EPI>
__global__ __launch_bounds__(256)
void k_mma_gemm(const __nv_bfloat16* __restrict__ Ahi, const __nv_bfloat16* __restrict__ Alo,
                const __nv_bfloat16* __restrict__ Bhi, const __nv_bfloat16* __restrict__ Blo,
                float* __restrict__ C,
                int lda, int ldb, int ldc, int nChunks) {
    extern __shared__ uint32_t sw[];
    const int tid = threadIdx.x;
    const int wid = tid >> 5, lane = tid & 31;
    const int g = lane >> 2, tig = lane & 3;
    const int wr = wid >> 2, wc = wid & 3;      // warp grid 2 (M) x 4 (N)
    const int nBase = blockIdx.x * 128;
    const int mBase = blockIdx.y * 128;
    const size_t kOff0 = (size_t)blockIdx.z * nChunks * BK;

    float acc[4][4][4];
    #pragma unroll
    for (int i = 0; i < 4; i++)
        #pragma unroll
        for (int j = 0; j < 4; j++)
            #pragma unroll
            for (int v = 0; v < 4; v++) acc[i][j][v] = 0.f;

    const uint32_t sbase = smem_u32(sw);

    auto issue = [&](int c) {
        if (c < nChunks) {
            const uint32_t sb = sbase + (uint32_t)((c % NSTAGE) * STAGE_W) * 4u;
            const size_t kEl = kOff0 + (size_t)c * BK;
            #pragma unroll
            for (int i = 0; i < 8; i++) {
                const int idx = i * 256 + tid;
                const int tile = idx >> 9;
                const int within = idx & 511;
                const int row = within >> 2;
                const int kg = within & 3;
                const __nv_bfloat16* p = (tile == 0) ? Ahi : (tile == 1) ? Alo
                                       : (tile == 2) ? Bhi : Blo;
                const size_t ro = (tile < 2) ? (size_t)(mBase + row) * lda
                                             : (size_t)(nBase + row) * ldb;
                const uint32_t dst = sb + (uint32_t)(tile * TILE_W + row * STRIDE_W + kg * 4) * 4u;
                cp_async16(dst, p + ro + kEl + kg * 8);
            }
        }
        CP_COMMIT();
    };

    issue(0); issue(1); issue(2);

    for (int c = 0; c < nChunks; ++c) {
        CP_WAIT2();
        __syncthreads();
        const uint32_t* st  = sw + (c % NSTAGE) * STAGE_W;
        const uint32_t* sAh = st;
        const uint32_t* sAl = st + TILE_W;
        const uint32_t* sBh = st + 2 * TILE_W;
        const uint32_t* sBl = st + 3 * TILE_W;

        #pragma unroll
        for (int ks = 0; ks < 2; ++ks) {
            const int kw = ks * 8 + tig;
            uint32_t Ar[4][4], Bh[4][2], Bl[4][2];
            #pragma unroll
            for (int mf = 0; mf < 4; mf++) {
                const int r0 = wr * 64 + mf * 16 + g;
                Ar[mf][0] = sAh[ r0      * STRIDE_W + kw];
                Ar[mf][1] = sAh[(r0 + 8) * STRIDE_W + kw];
                Ar[mf][2] = sAh[ r0      * STRIDE_W + kw + 4];
                Ar[mf][3] = sAh[(r0 + 8) * STRIDE_W + kw + 4];
            }
            #pragma unroll
            for (int nf = 0; nf < 4; nf++) {
                const int n0 = wc * 32 + nf * 8 + g;
                Bh[nf][0] = sBh[n0 * STRIDE_W + kw];
                Bh[nf][1] = sBh[n0 * STRIDE_W + kw + 4];
                Bl[nf][0] = sBl[n0 * STRIDE_W + kw];
                Bl[nf][1] = sBl[n0 * STRIDE_W + kw + 4];
            }
            // term hi*hi and hi*lo
            #pragma unroll
            for (int mf = 0; mf < 4; mf++)
                #pragma unroll
                for (int nf = 0; nf < 4; nf++) {
                    MMA16816(acc[mf][nf], Ar[mf], Bh[nf]);
                    MMA16816(acc[mf][nf], Ar[mf], Bl[nf]);
                }
            // term lo*hi
            #pragma unroll
            for (int mf = 0; mf < 4; mf++) {
                const int r0 = wr * 64 + mf * 16 + g;
                Ar[mf][0] = sAl[ r0      * STRIDE_W + kw];
                Ar[mf][1] = sAl[(r0 + 8) * STRIDE_W + kw];
                Ar[mf][2] = sAl[ r0      * STRIDE_W + kw + 4];
                Ar[mf][3] = sAl[(r0 + 8) * STRIDE_W + kw + 4];
            }
            #pragma unroll
            for (int mf = 0; mf < 4; mf++)
                #pragma unroll
                for (int nf = 0; nf < 4; nf++)
                    MMA16816(acc[mf][nf], Ar[mf], Bh[nf]);
        }
        __syncthreads();
        issue(c + NSTAGE);
    }

    // epilogue: c0,c1 -> (row, col..col+1); c2,c3 -> (row+8, col..col+1)
    #pragma unroll
    for (int mf = 0; mf < 4; mf++) {
        const int row = mBase + wr * 64 + mf * 16 + g;
        #pragma unroll
        for (int nf = 0; nf < 4; nf++) {
            const int col = nBase + wc * 32 + nf * 8 + tig * 2;
            float* p0 = &C[(size_t)row * ldc + col];
            float* p1 = &C[(size_t)(row + 8) * ldc + col];
            if (EPI == 0) {
                *(float2*)p0 = make_float2(acc[mf][nf][0], acc[mf][nf][1]);
                *(float2*)p1 = make_float2(acc[mf][nf][2], acc[mf][nf][3]);
            } else {
                atomicAdd(p0,     acc[mf][nf][0]);
                atomicAdd(p0 + 1, acc[mf][nf][1]);
                atomicAdd(p1,     acc[mf][nf][2]);
                atomicAdd(p1 + 1, acc[mf][nf][3]);
            }
        }
    }
}

// ================= glue kernels =================
__global__ void k_zero(float* __restrict__ h6, float* __restrict__ h7,
                       float* __restrict__ stats) {
    int i = blockIdx.x * blockDim.x + threadIdx.x;
    if (i < NBOX * REP) { h6[i] = 0.f; h7[i] = 0.f; }
    if (i < 2 * REP)    stats[i] = 0.f;
}

// ROIAlign -> Ahi/Alo [50176, 896], k = c*7 + z
__global__ void k_roi(const float* __restrict__ feat, const float* __restrict__ boxes,
                      const int* __restrict__ bidx,
                      __nv_bfloat16* __restrict__ Ahi, __nv_bfloat16* __restrict__ Alo) {
    const int xy = blockIdx.x, n = blockIdx.y, c = threadIdx.x;
    const int qx = xy / RES7, qy = xy % RES7;
    __shared__ float pool[896];

    const float x1 = boxes[n*6+0]*PX_SCALE, y1 = boxes[n*6+1]*PX_SCALE,
                z1 = boxes[n*6+2]*PX_SCALE, x2 = boxes[n*6+3]*PX_SCALE,
                y2 = boxes[n*6+4]*PX_SCALE, z2 = boxes[n*6+5]*PX_SCALE;
    const float bx = fmaxf(x2-x1, 1.f) * (1.f/RES7);
    const float by = fmaxf(y2-y1, 1.f) * (1.f/RES7);
    const float bz = fmaxf(z2-z1, 1.f) * (1.f/RES7);
    const float px = x1 + ((float)qx + 0.5f) * bx;
    const float py = y1 + ((float)qy + 0.5f) * by;
    const float fx = floorf(px), lx = px - fx;
    const float fy = floorf(py), ly = py - fy;
    int ix0 = min(max((int)fx, 0), DIMX-1);
    int ix1 = min(max((int)fx + 1, 0), DIMX-1);
    int iy0 = min(max((int)fy, 0), DIMY-1);
    int iy1 = min(max((int)fy + 1, 0), DIMY-1);
    const int b = bidx[n];
    int base[4]; float wxy[4];
    base[0] = ((b*DIMX+ix0)*DIMY+iy0)*DIMZ; wxy[0] = (1.f-lx)*(1.f-ly);
    base[1] = ((b*DIMX+ix0)*DIMY+iy1)*DIMZ; wxy[1] = (1.f-lx)*ly;
    base[2] = ((b*DIMX+ix1)*DIMY+iy0)*DIMZ; wxy[2] = lx*(1.f-ly);
    base[3] = ((b*DIMX+ix1)*DIMY+iy1)*DIMZ; wxy[3] = lx*ly;

    #pragma unroll
    for (int z = 0; z < RES7; z++) {
        const float pz = z1 + ((float)z + 0.5f) * bz;
        const float fz = floorf(pz), lz = pz - fz;
        int iz0 = min(max((int)fz, 0), DIMZ-1);
        int iz1 = min(max((int)fz + 1, 0), DIMZ-1);
        float v = 0.f;
        #pragma unroll
        for (int q = 0; q < 4; q++) {
            float f0 = feat[(size_t)(base[q] + iz0) * C_IN + c];
            float f1 = feat[(size_t)(base[q] + iz1) * C_IN + c];
            v += wxy[q] * ((1.f - lz) * f0 + lz * f1);
        }
        pool[c * RES7 + z] = v;
    }
    __syncthreads();
    const size_t rowOff = (size_t)(n * 49 + xy) * KCONV;
    for (int i = threadIdx.x; i < KCONV; i += 128) {
        __nv_bfloat16 h, l; split_bf16(pool[i], h, l);
        Ahi[rowOff + i] = h; Alo[rowOff + i] = l;
    }
}

// transpose + split: src [R,NC] fp32 -> dst [NC,R] bf16 hi/lo
__global__ void k_tcvt(const float* __restrict__ src,
                       __nv_bfloat16* __restrict__ dhi, __nv_bfloat16* __restrict__ dlo,
                       int R, int NC) {
    __shared__ float t[32][33];
    const int c = blockIdx.x * 32 + threadIdx.x;
    const int r0 = blockIdx.y * 32;
    for (int j = threadIdx.y; j < 32; j += 8)
        t[j][threadIdx.x] = src[(size_t)(r0 + j) * NC + c];
    __syncthreads();
    for (int j = threadIdx.y; j < 32; j += 8) {
        float v = t[threadIdx.x][j];
        size_t o = (size_t)(blockIdx.x * 32 + j) * R + r0 + threadIdx.x;
        __nv_bfloat16 h, l; split_bf16(v, h, l);
        dhi[o] = h; dlo[o] = l;
    }
}

// elementwise split (conv_w is already [r, k])
__global__ void k_cvt(const float* __restrict__ src,
                      __nv_bfloat16* __restrict__ dhi, __nv_bfloat16* __restrict__ dlo, int n) {
    int i = blockIdx.x * blockDim.x + threadIdx.x;
    if (i < n) { __nv_bfloat16 h, l; split_bf16(src[i], h, l); dhi[i] = h; dlo[i] = l; }
}

// column sums over Y
__global__ void k_stats(const float* __restrict__ Y, float* __restrict__ stats) {
    const int col = blockIdx.x * 128 + threadIdx.x;
    const int rBase = blockIdx.y * 128;
    float s = 0.f, q = 0.f;
    #pragma unroll 8
    for (int i = 0; i < 128; i++) {
        float v = Y[(size_t)(rBase + i) * REP + col];
        s += v; q += v * v;
    }
    atomicAdd(&stats[col], s);
    atomicAdd(&stats[REP + col], q);
}

__global__ void k_finalize(const float* __restrict__ stats,
                           float* __restrict__ mean, float* __restrict__ rsig) {
    int r = blockIdx.x * blockDim.x + threadIdx.x;
    if (r < REP) {
        const float inv = 1.0f / (float)MROWS;
        float mu = stats[r] * inv;
        float v  = stats[REP + r] * inv - mu * mu;
        mean[r] = mu;
        rsig[r] = rsqrtf(v + 1e-5f);
    }
}

// normalize + relu + transpose -> X2 hi/lo [n, r*49+xy]
__global__ __launch_bounds__(256) void k_norm(
    const float* __restrict__ Y,
    __nv_bfloat16* __restrict__ X2hi, __nv_bfloat16* __restrict__ X2lo,
    const float* __restrict__ mean, const float* __restrict__ rsig,
    const float* __restrict__ gamma, const float* __restrict__ beta) {
    const int n = blockIdx.x;
    __shared__ float tile[49][129];
    __shared__ float sm[128], sr[128], sg[128], sb[128];
    for (int rc = 0; rc < 7; rc++) {
        const int rbase = rc * 128;
        if (threadIdx.x < 128) {
            int r = rbase + threadIdx.x;
            sm[threadIdx.x] = mean[r];  sr[threadIdx.x] = rsig[r];
            sg[threadIdx.x] = gamma[r]; sb[threadIdx.x] = beta[r];
        }
        for (int idx = threadIdx.x; idx < 49 * 128; idx += 256) {
            int xy = idx >> 7, rr = idx & 127;
            tile[xy][rr] = Y[(size_t)(n * 49 + xy) * REP + rbase + rr];
        }
        __syncthreads();
        for (int o = threadIdx.x; o < 128 * 49; o += 256) {
            int rr = o / 49, xy = o % 49;
            float v = (tile[xy][rr] - sm[rr]) * sr[rr] * sg[rr] + sb[rr];
            v = fmaxf(v, 0.f);
            __nv_bfloat16 h, l; split_bf16(v, h, l);
            size_t o2 = (size_t)n * INSZ + rbase * 49 + o;
            X2hi[o2] = h; X2lo[o2] = l;
        }
        __syncthreads();
    }
}

// bias + relu + split: H6 -> X3 hi/lo
__global__ void k_bias_relu_cvt(const float* __restrict__ in, const float* __restrict__ bias,
                                __nv_bfloat16* __restrict__ dhi, __nv_bfloat16* __restrict__ dlo) {
    int i = blockIdx.x * blockDim.x + threadIdx.x;
    if (i < NBOX * REP) {
        float v = fmaxf(in[i] + bias[i % REP], 0.f);
        __nv_bfloat16 h, l; split_bf16(v, h, l);
        dhi[i] = h; dlo[i] = l;
    }
}

// bias + relu: H7 -> out
__global__ void k_bias_relu(const float* __restrict__ in, const float* __restrict__ bias,
                            float* __restrict__ out) {
    int i = blockIdx.x * blockDim.x + threadIdx.x;
    if (i < NBOX * REP)
        out[i] = fmaxf(in[i] + bias[i % REP], 0.f);
}

// ---------------- launch ----------------
extern "C" void kernel_launch(void* const* d_in, const int* in_sizes, int n_in,
                              void* d_out, int out_size) {
    const float* feat   = (const float*)d_in[0];
    const float* boxes  = (const float*)d_in[1];
    const float* conv_w = (const float*)d_in[2];
    // conv_b (d_in[3]) cancels in the mean subtraction
    const float* gamma  = (const float*)d_in[4];
    const float* beta   = (const float*)d_in[5];
    const float* fc6_w  = (const float*)d_in[6];
    const float* fc6_b  = (const float*)d_in[7];
    const float* fc7_w  = (const float*)d_in[8];
    const float* fc7_b  = (const float*)d_in[9];
    const int*   bidx   = (const int*)d_in[10];
    float* out = (float*)d_out;

    auto sym = [](const void* s) { void* p = nullptr; cudaGetSymbolAddress(&p, s); return p; };
    float* Y      = (float*)sym(g_Y);
    __nv_bfloat16* Ahi  = (__nv_bfloat16*)sym(g_Ahi);
    __nv_bfloat16* Alo  = (__nv_bfloat16*)sym(g_Alo);
    __nv_bfloat16* X2hi = (__nv_bfloat16*)sym(g_X2hi);
    __nv_bfloat16* X2lo = (__nv_bfloat16*)sym(g_X2lo);
    __nv_bfloat16* W6Thi= (__nv_bfloat16*)sym(g_W6Thi);
    __nv_bfloat16* W6Tlo= (__nv_bfloat16*)sym(g_W6Tlo);
    __nv_bfloat16* WChi = (__nv_bfloat16*)sym(g_WChi);
    __nv_bfloat16* WClo = (__nv_bfloat16*)sym(g_WClo);
    __nv_bfloat16* W7Thi= (__nv_bfloat16*)sym(g_W7Thi);
    __nv_bfloat16* W7Tlo= (__nv_bfloat16*)sym(g_W7Tlo);
    __nv_bfloat16* X3hi = (__nv_bfloat16*)sym(g_X3hi);
    __nv_bfloat16* X3lo = (__nv_bfloat16*)sym(g_X3lo);
    float* H6    = (float*)sym(g_H6);
    float* H7    = (float*)sym(g_H7);
    float* STATS = (float*)sym(g_stats);
    float* MEAN  = (float*)sym(g_mean);
    float* RSIG  = (float*)sym(g_rsig);

    cudaFuncSetAttribute(k_mma_gemm<0>, cudaFuncAttributeMaxDynamicSharedMemorySize, GEMM_SMEM);
    cudaFuncSetAttribute(k_mma_gemm<1>, cudaFuncAttributeMaxDynamicSharedMemorySize, GEMM_SMEM);

    // 1. zero accumulators + stats
    k_zero<<<3584, 256>>>(H6, H7, STATS);
    // 2. weight conversions
    k_cvt<<<(REP * KCONV + 255) / 256, 256>>>(conv_w, WChi, WClo, REP * KCONV);
    k_tcvt<<<dim3(REP / 32, INSZ / 32), dim3(32, 8)>>>(fc6_w, W6Thi, W6Tlo, INSZ, REP);
    k_tcvt<<<dim3(REP / 32, REP / 32), dim3(32, 8)>>>(fc7_w, W7Thi, W7Tlo, REP, REP);
    // 3. ROIAlign -> A hi/lo
    k_roi<<<dim3(49, NBOX), 128>>>(feat, boxes, bidx, Ahi, Alo);
    // 4. conv einsum GEMM: Y = A @ Wc^T   [50176 x 896], K=896 (28 chunks)
    k_mma_gemm<0><<<dim3(7, 392, 1), 256, GEMM_SMEM>>>(
        Ahi, Alo, WChi, WClo, Y, KCONV, KCONV, REP, 28);
    // 5. norm stats
    k_stats<<<dim3(7, 392), 128>>>(Y, STATS);
    k_finalize<<<7, 128>>>(STATS, MEAN, RSIG);
    // 6. normalize + relu + transpose -> X2 hi/lo
    k_norm<<<NBOX, 256>>>(Y, X2hi, X2lo, MEAN, RSIG, gamma, beta);
    // 7. fc6 GEMM, split-K 14 (98 chunks each): H6 += X2 @ W6T^T
    k_mma_gemm<1><<<dim3(7, 8, 14), 256, GEMM_SMEM>>>(
        X2hi, X2lo, W6Thi, W6Tlo, H6, INSZ, INSZ, REP, 98);
    // 8. bias+relu -> X3 hi/lo
    k_bias_relu_cvt<<<3584, 256>>>(H6, fc6_b, X3hi, X3lo);
    // 9. fc7 GEMM, split-K 4 (7 chunks each)
    k_mma_gemm<1><<<dim3(7, 8, 4), 256, GEMM_SMEM>>>(
        X3hi, X3lo, W7Thi, W7Tlo, H7, REP, REP, REP, 7);
    k_bias_relu<<<3584, 256>>>(H7, fc7_b, out);
}

// round 4
// speedup vs baseline: 2.5816x; 1.2657x over previous
#include <cuda_runtime.h>
#include <cuda_bf16.h>
#include <cstdint>
#include <cstddef>

// ---------------- problem constants ----------------
constexpr int RES7  = 7;
constexpr int NBOX  = 1024;
constexpr int C_IN  = 128;
constexpr int REP   = 896;                  // 128*7
constexpr int MROWS = NBOX * 49;            // 50176
constexpr int KCONV = 896;                  // C_IN*7
constexpr int INSZ  = 43904;                // REP*49
constexpr int DIMX = 80, DIMY = 80, DIMZ = 20;
constexpr float PX_SCALE = 5.0f;            // 20 * 0.25

// ---------------- static scratch (all fp32, tf32-rounded where GEMM inputs) --
__device__ float g_A  [(size_t)MROWS * KCONV];   // roi out (tf32)
__device__ float g_Y  [(size_t)MROWS * REP];     // conv out
__device__ float g_X2 [(size_t)NBOX * INSZ];     // normalized (tf32)
__device__ float g_WC [(size_t)REP * KCONV];     // conv_w (tf32)
__device__ float g_W6T[(size_t)REP * INSZ];      // fc6_w^T (tf32)
__device__ float g_W7T[(size_t)REP * REP];       // fc7_w^T (tf32)
__device__ float g_X3 [(size_t)NBOX * REP];      // relu(fc6) (tf32)
__device__ float g_H6 [(size_t)NBOX * REP];
__device__ float g_H7 [(size_t)NBOX * REP];
__device__ float g_stats[2 * REP];
__device__ float g_mean[REP];
__device__ float g_rsig[REP];

// ---------------- helpers ----------------
__device__ __forceinline__ uint32_t smem_u32(const void* p) {
    uint32_t a;
    asm("{ .reg .u64 t; cvta.to.shared.u64 t, %1; cvt.u32.u64 %0, t; }" : "=r"(a) : "l"(p));
    return a;
}
__device__ __forceinline__ void cp_async16(uint32_t dst, const void* src) {
    asm volatile("cp.async.cg.shared.global [%0], [%1], 16;" :: "r"(dst), "l"(src) : "memory");
}
#define CP_COMMIT() asm volatile("cp.async.commit_group;" ::: "memory")
#define CP_WAIT3()  asm volatile("cp.async.wait_group 3;" ::: "memory")

__device__ __forceinline__ float to_tf32(float x) {
    uint32_t r;
    asm("cvt.rna.tf32.f32 %0, %1;" : "=r"(r) : "f"(x));
    return __uint_as_float(r);
}

#define MMA1688(c, a, b)                                                    \
    asm volatile("mma.sync.aligned.m16n8k8.row.col.f32.tf32.tf32.f32 "      \
        "{%0,%1,%2,%3},{%4,%5,%6,%7},{%8,%9},{%0,%1,%2,%3};"                \
        : "+f"((c)[0]), "+f"((c)[1]), "+f"((c)[2]), "+f"((c)[3])            \
        : "r"((a)[0]), "r"((a)[1]), "r"((a)[2]), "r"((a)[3]),               \
          "r"((b)[0]), "r"((b)[1]))

// ================= TF32 mma.sync GEMM =================
// D[m,n] = sum_k A[m,k]*B[n,k], A/B pre-rounded to tf32.
// CTA 128x128, 8 warps (2x4), warp tile 64x32, BK=32, 4-stage cp.async.
// EPI: 0 = plain store, 1 = store + fused column stats, 2 = atomicAdd (split-K).
constexpr int BK        = 32;
constexpr int STRIDE_W  = 36;                 // fp32 words per smem row (144B, conflict-free)
constexpr int TILE_W    = 128 * STRIDE_W;
constexpr int STAGE_W   = 2 * TILE_W;         // A,B
constexpr int NSTAGE    = 4;
constexpr int GEMM_SMEM = NSTAGE * STAGE_W * 4;   // 147456 B

template<int EPI>
__global__ __launch_bounds__(256, 1)
void k_mma_gemm(const float* __restrict__ A, const float* __restrict__ B,
                float* __restrict__ C, float* __restrict__ stats,
                int lda, int ldb, int ldc, int nChunks) {
    extern __shared__ uint32_t sw[];
    const int tid = threadIdx.x;
    const int wid = tid >> 5, lane = tid & 31;
    const int g = lane >> 2, tig = lane & 3;
    const int wr = wid >> 2, wc = wid & 3;      // warp grid 2 (M) x 4 (N)
    const int nBase = blockIdx.x * 128;
    const int mBase = blockIdx.y * 128;
    const size_t kOff0 = (size_t)blockIdx.z * nChunks * BK;

    float acc[4][4][4];
    #pragma unroll
    for (int i = 0; i < 4; i++)
        #pragma unroll
        for (int j = 0; j < 4; j++)
            #pragma unroll
            for (int v = 0; v < 4; v++) acc[i][j][v] = 0.f;

    const uint32_t sbase = smem_u32(sw);

    auto issue = [&](int c) {
        if (c < nChunks) {
            const uint32_t sb = sbase + (uint32_t)((c % NSTAGE) * STAGE_W) * 4u;
            const size_t kEl = kOff0 + (size_t)c * BK;
            #pragma unroll
            for (int i = 0; i < 8; i++) {
                const int idx = i * 256 + tid;
                const int mat = idx >> 10;            // 0=A, 1=B
                const int within = idx & 1023;
                const int row = within >> 3;
                const int kg = within & 7;
                const float* p = mat ? B : A;
                const size_t ro = mat ? (size_t)(nBase + row) * ldb
                                      : (size_t)(mBase + row) * lda;
                const uint32_t dst = sb + (uint32_t)(mat * TILE_W + row * STRIDE_W + kg * 4) * 4u;
                cp_async16(dst, p + ro + kEl + kg * 4);
            }
        }
        CP_COMMIT();
    };

    issue(0); issue(1); issue(2); issue(3);

    for (int c = 0; c < nChunks; ++c) {
        CP_WAIT3();
        __syncthreads();
        const uint32_t* sA = sw + (c % NSTAGE) * STAGE_W;
        const uint32_t* sB = sA + TILE_W;

        #pragma unroll
        for (int step = 0; step < 4; ++step) {
            const int kw = step * 8 + tig;
            uint32_t Ar[4][4], Bf[4][2];
            #pragma unroll
            for (int mf = 0; mf < 4; mf++) {
                const int r0 = wr * 64 + mf * 16 + g;
                Ar[mf][0] = sA[ r0      * STRIDE_W + kw];
                Ar[mf][1] = sA[(r0 + 8) * STRIDE_W + kw];
                Ar[mf][2] = sA[ r0      * STRIDE_W + kw + 4];
                Ar[mf][3] = sA[(r0 + 8) * STRIDE_W + kw + 4];
            }
            #pragma unroll
            for (int nf = 0; nf < 4; nf++) {
                const int n0 = wc * 32 + nf * 8 + g;
                Bf[nf][0] = sB[n0 * STRIDE_W + kw];
                Bf[nf][1] = sB[n0 * STRIDE_W + kw + 4];
            }
            #pragma unroll
            for (int mf = 0; mf < 4; mf++)
                #pragma unroll
                for (int nf = 0; nf < 4; nf++)
                    MMA1688(acc[mf][nf], Ar[mf], Bf[nf]);
        }
        __syncthreads();
        issue(c + NSTAGE);
    }

    // ---- epilogue ----
    #pragma unroll
    for (int mf = 0; mf < 4; mf++) {
        const int row = mBase + wr * 64 + mf * 16 + g;
        #pragma unroll
        for (int nf = 0; nf < 4; nf++) {
            const int col = nBase + wc * 32 + nf * 8 + tig * 2;
            float* p0 = &C[(size_t)row * ldc + col];
            float* p1 = &C[(size_t)(row + 8) * ldc + col];
            if (EPI == 2) {
                atomicAdd(p0,     acc[mf][nf][0]);
                atomicAdd(p0 + 1, acc[mf][nf][1]);
                atomicAdd(p1,     acc[mf][nf][2]);
                atomicAdd(p1 + 1, acc[mf][nf][3]);
            } else {
                *(float2*)p0 = make_float2(acc[mf][nf][0], acc[mf][nf][1]);
                *(float2*)p1 = make_float2(acc[mf][nf][2], acc[mf][nf][3]);
            }
        }
    }

    if constexpr (EPI == 1) {   // fused per-column sum / sumsq
        __shared__ float sSum[128], sSq[128];
        if (tid < 128) { sSum[tid] = 0.f; sSq[tid] = 0.f; }
        __syncthreads();
        #pragma unroll
        for (int nf = 0; nf < 4; nf++) {
            #pragma unroll
            for (int b = 0; b < 2; b++) {
                float s = 0.f, q = 0.f;
                #pragma unroll
                for (int mf = 0; mf < 4; mf++) {
                    float v0 = acc[mf][nf][b], v1 = acc[mf][nf][b + 2];
                    s += v0 + v1; q += v0 * v0 + v1 * v1;
                }
                // reduce across g (lanes with same tig): xor 16, 8, 4
                s += __shfl_xor_sync(0xffffffffu, s, 16);
                s += __shfl_xor_sync(0xffffffffu, s, 8);
                s += __shfl_xor_sync(0xffffffffu, s, 4);
                q += __shfl_xor_sync(0xffffffffu, q, 16);
                q += __shfl_xor_sync(0xffffffffu, q, 8);
                q += __shfl_xor_sync(0xffffffffu, q, 4);
                if (g == 0) {
                    const int col = wc * 32 + nf * 8 + tig * 2 + b;
                    atomicAdd(&sSum[col], s);
                    atomicAdd(&sSq[col],  q);
                }
            }
        }
        __syncthreads();
        if (tid < 128) {
            atomicAdd(&stats[nBase + tid],       sSum[tid]);
            atomicAdd(&stats[REP + nBase + tid], sSq[tid]);
        }
    }
}

// ================= glue kernels =================
__global__ void k_zero(float* __restrict__ h6, float* __restrict__ h7,
                       float* __restrict__ stats) {
    int i = blockIdx.x * blockDim.x + threadIdx.x;
    if (i < NBOX * REP) { h6[i] = 0.f; h7[i] = 0.f; }
    if (i < 2 * REP)    stats[i] = 0.f;
}

// ROIAlign -> A [50176, 896] (tf32-rounded), k = c*7 + z
__global__ void k_roi(const float* __restrict__ feat, const float* __restrict__ boxes,
                      const int* __restrict__ bidx, float* __restrict__ A) {
    const int xy = blockIdx.x, n = blockIdx.y, c = threadIdx.x;
    const int qx = xy / RES7, qy = xy % RES7;

    const float x1 = boxes[n*6+0]*PX_SCALE, y1 = boxes[n*6+1]*PX_SCALE,
                z1 = boxes[n*6+2]*PX_SCALE, x2 = boxes[n*6+3]*PX_SCALE,
                y2 = boxes[n*6+4]*PX_SCALE, z2 = boxes[n*6+5]*PX_SCALE;
    const float bx = fmaxf(x2-x1, 1.f) * (1.f/RES7);
    const float by = fmaxf(y2-y1, 1.f) * (1.f/RES7);
    const float bz = fmaxf(z2-z1, 1.f) * (1.f/RES7);
    const float px = x1 + ((float)qx + 0.5f) * bx;
    const float py = y1 + ((float)qy + 0.5f) * by;
    const float fx = floorf(px), lx = px - fx;
    const float fy = floorf(py), ly = py - fy;
    int ix0 = min(max((int)fx, 0), DIMX-1);
    int ix1 = min(max((int)fx + 1, 0), DIMX-1);
    int iy0 = min(max((int)fy, 0), DIMY-1);
    int iy1 = min(max((int)fy + 1, 0), DIMY-1);
    const int b = bidx[n];
    int base[4]; float wxy[4];
    base[0] = ((b*DIMX+ix0)*DIMY+iy0)*DIMZ; wxy[0] = (1.f-lx)*(1.f-ly);
    base[1] = ((b*DIMX+ix0)*DIMY+iy1)*DIMZ; wxy[1] = (1.f-lx)*ly;
    base[2] = ((b*DIMX+ix1)*DIMY+iy0)*DIMZ; wxy[2] = lx*(1.f-ly);
    base[3] = ((b*DIMX+ix1)*DIMY+iy1)*DIMZ; wxy[3] = lx*ly;

    float* Arow = A + (size_t)(n * 49 + xy) * KCONV;
    #pragma unroll
    for (int z = 0; z < RES7; z++) {
        const float pz = z1 + ((float)z + 0.5f) * bz;
        const float fz = floorf(pz), lz = pz - fz;
        int iz0 = min(max((int)fz, 0), DIMZ-1);
        int iz1 = min(max((int)fz + 1, 0), DIMZ-1);
        float v = 0.f;
        #pragma unroll
        for (int q = 0; q < 4; q++) {
            float f0 = feat[(size_t)(base[q] + iz0) * C_IN + c];
            float f1 = feat[(size_t)(base[q] + iz1) * C_IN + c];
            v += wxy[q] * ((1.f - lz) * f0 + lz * f1);
        }
        Arow[c * RES7 + z] = to_tf32(v);
    }
}

// transpose + tf32-round: src [R,NC] -> dst [NC,R]
__global__ void k_tcvt(const float* __restrict__ src, float* __restrict__ dst,
                       int R, int NC) {
    __shared__ float t[32][33];
    const int c = blockIdx.x * 32 + threadIdx.x;
    const int r0 = blockIdx.y * 32;
    for (int j = threadIdx.y; j < 32; j += 8)
        t[j][threadIdx.x] = src[(size_t)(r0 + j) * NC + c];
    __syncthreads();
    for (int j = threadIdx.y; j < 32; j += 8)
        dst[(size_t)(blockIdx.x * 32 + j) * R + r0 + threadIdx.x] = to_tf32(t[threadIdx.x][j]);
}

// elementwise tf32-round (conv_w already [r, k])
__global__ void k_cvt(const float* __restrict__ src, float* __restrict__ dst, int n) {
    int i = blockIdx.x * blockDim.x + threadIdx.x;
    if (i < n) dst[i] = to_tf32(src[i]);
}

__global__ void k_finalize(const float* __restrict__ stats,
                           float* __restrict__ mean, float* __restrict__ rsig) {
    int r = blockIdx.x * blockDim.x + threadIdx.x;
    if (r < REP) {
        const float inv = 1.0f / (float)MROWS;
        float mu = stats[r] * inv;
        float v  = stats[REP + r] * inv - mu * mu;
        mean[r] = mu;
        rsig[r] = rsqrtf(v + 1e-5f);
    }
}

// normalize + relu + transpose -> X2 [n, r*49+xy] (tf32)
__global__ __launch_bounds__(256) void k_norm(
    const float* __restrict__ Y, float* __restrict__ X2,
    const float* __restrict__ mean, const float* __restrict__ rsig,
    const float* __restrict__ gamma, const float* __restrict__ beta) {
    const int n = blockIdx.x;
    __shared__ float tile[49][129];
    __shared__ float sm[128], sr[128], sg[128], sb[128];
    for (int rc = 0; rc < 7; rc++) {
        const int rbase = rc * 128;
        if (threadIdx.x < 128) {
            int r = rbase + threadIdx.x;
            sm[threadIdx.x] = mean[r];  sr[threadIdx.x] = rsig[r];
            sg[threadIdx.x] = gamma[r]; sb[threadIdx.x] = beta[r];
        }
        for (int idx = threadIdx.x; idx < 49 * 128; idx += 256) {
            int xy = idx >> 7, rr = idx & 127;
            tile[xy][rr] = Y[(size_t)(n * 49 + xy) * REP + rbase + rr];
        }
        __syncthreads();
        for (int o = threadIdx.x; o < 128 * 49; o += 256) {
            int rr = o / 49, xy = o % 49;
            float v = (tile[xy][rr] - sm[rr]) * sr[rr] * sg[rr] + sb[rr];
            X2[(size_t)n * INSZ + rbase * 49 + o] = to_tf32(fmaxf(v, 0.f));
        }
        __syncthreads();
    }
}

// bias + relu + tf32-round: H6 -> X3
__global__ void k_bias_relu_cvt(const float* __restrict__ in, const float* __restrict__ bias,
                                float* __restrict__ dst) {
    int i = blockIdx.x * blockDim.x + threadIdx.x;
    if (i < NBOX * REP)
        dst[i] = to_tf32(fmaxf(in[i] + bias[i % REP], 0.f));
}

// bias + relu: H7 -> out
__global__ void k_bias_relu(const float* __restrict__ in, const float* __restrict__ bias,
                            float* __restrict__ out) {
    int i = blockIdx.x * blockDim.x + threadIdx.x;
    if (i < NBOX * REP)
        out[i] = fmaxf(in[i] + bias[i % REP], 0.f);
}

// ---------------- launch ----------------
extern "C" void kernel_launch(void* const* d_in, const int* in_sizes, int n_in,
                              void* d_out, int out_size) {
    const float* feat   = (const float*)d_in[0];
    const float* boxes  = (const float*)d_in[1];
    const float* conv_w = (const float*)d_in[2];
    // conv_b (d_in[3]) cancels in the mean subtraction
    const float* gamma  = (const float*)d_in[4];
    const float* beta   = (const float*)d_in[5];
    const float* fc6_w  = (const float*)d_in[6];
    const float* fc6_b  = (const float*)d_in[7];
    const float* fc7_w  = (const float*)d_in[8];
    const float* fc7_b  = (const float*)d_in[9];
    const int*   bidx   = (const int*)d_in[10];
    float* out = (float*)d_out;

    auto sym = [](const void* s) { void* p = nullptr; cudaGetSymbolAddress(&p, s); return p; };
    float* A    = (float*)sym(g_A);
    float* Y    = (float*)sym(g_Y);
    float* X2   = (float*)sym(g_X2);
    float* WC   = (float*)sym(g_WC);
    float* W6T  = (float*)sym(g_W6T);
    float* W7T  = (float*)sym(g_W7T);
    float* X3   = (float*)sym(g_X3);
    float* H6   = (float*)sym(g_H6);
    float* H7   = (float*)sym(g_H7);
    float* STATS= (float*)sym(g_stats);
    float* MEAN = (float*)sym(g_mean);
    float* RSIG = (float*)sym(g_rsig);

    cudaFuncSetAttribute(k_mma_gemm<1>, cudaFuncAttributeMaxDynamicSharedMemorySize, GEMM_SMEM);
    cudaFuncSetAttribute(k_mma_gemm<2>, cudaFuncAttributeMaxDynamicSharedMemorySize, GEMM_SMEM);

    // 1. zero accumulators + stats
    k_zero<<<3584, 256>>>(H6, H7, STATS);
    // 2. weight conversions (tf32 rounding)
    k_cvt<<<(REP * KCONV + 255) / 256, 256>>>(conv_w, WC, REP * KCONV);
    k_tcvt<<<dim3(REP / 32, INSZ / 32), dim3(32, 8)>>>(fc6_w, W6T, INSZ, REP);
    k_tcvt<<<dim3(REP / 32, REP / 32), dim3(32, 8)>>>(fc7_w, W7T, REP, REP);
    // 3. ROIAlign -> A (tf32)
    k_roi<<<dim3(49, NBOX), 128>>>(feat, boxes, bidx, A);
    // 4. conv einsum GEMM + fused stats: Y = A @ WC^T   (K=896, 28 chunks)
    k_mma_gemm<1><<<dim3(7, 392, 1), 256, GEMM_SMEM>>>(
        A, WC, Y, STATS, KCONV, KCONV, REP, 28);
    // 5. mean / rsig
    k_finalize<<<7, 128>>>(STATS, MEAN, RSIG);
    // 6. normalize + relu + transpose -> X2 (tf32)
    k_norm<<<NBOX, 256>>>(Y, X2, MEAN, RSIG, gamma, beta);
    // 7. fc6 GEMM, split-K 14 (98 chunks each): H6 += X2 @ W6T^T
    k_mma_gemm<2><<<dim3(7, 8, 14), 256, GEMM_SMEM>>>(
        X2, W6T, H6, nullptr, INSZ, INSZ, REP, 98);
    // 8. bias+relu -> X3 (tf32)
    k_bias_relu_cvt<<<3584, 256>>>(H6, fc6_b, X3);
    // 9. fc7 GEMM, split-K 4 (7 chunks each)
    k_mma_gemm<2><<<dim3(7, 8, 4), 256, GEMM_SMEM>>>(
        X3, W7T, H7, nullptr, REP, REP, REP, 7);
    k_bias_relu<<<3584, 256>>>(H7, fc7_b, out);
}

// round 5
// speedup vs baseline: 3.0486x; 1.1809x over previous
#include <cuda_runtime.h>
#include <cuda_bf16.h>
#include <cstdint>
#include <cstddef>

// ---------------- problem constants ----------------
constexpr int RES7  = 7;
constexpr int NBOX  = 1024;
constexpr int C_IN  = 128;
constexpr int REP   = 896;                  // 128*7
constexpr int MROWS = NBOX * 49;            // 50176
constexpr int KCONV = 896;                  // C_IN*7
constexpr int INSZ  = 43904;                // REP*49
constexpr int DIMX = 80, DIMY = 80, DIMZ = 20;
constexpr float PX_SCALE = 5.0f;            // 20 * 0.25

// ---------------- static scratch (all fp32, tf32-rounded where GEMM inputs) --
__device__ float g_A  [(size_t)MROWS * KCONV];   // roi out (tf32)
__device__ float g_Y  [(size_t)MROWS * REP];     // conv out
__device__ float g_X2 [(size_t)NBOX * INSZ];     // normalized (tf32)
__device__ float g_WC [(size_t)REP * KCONV];     // conv_w (tf32)
__device__ float g_W6T[(size_t)REP * INSZ];      // fc6_w^T (tf32)
__device__ float g_W7T[(size_t)REP * REP];       // fc7_w^T (tf32)
__device__ float g_X3 [(size_t)NBOX * REP];      // relu(fc6) (tf32)
__device__ float g_H6 [(size_t)NBOX * REP];
__device__ float g_H7 [(size_t)NBOX * REP];
__device__ float g_stats[2 * REP];
__device__ float g_mean[REP];
__device__ float g_rsig[REP];

// ---------------- helpers ----------------
__device__ __forceinline__ uint32_t smem_u32(const void* p) {
    uint32_t a;
    asm("{ .reg .u64 t; cvta.to.shared.u64 t, %1; cvt.u32.u64 %0, t; }" : "=r"(a) : "l"(p));
    return a;
}
__device__ __forceinline__ void cp_async16(uint32_t dst, const void* src) {
    asm volatile("cp.async.cg.shared.global [%0], [%1], 16;" :: "r"(dst), "l"(src) : "memory");
}
#define CP_COMMIT() asm volatile("cp.async.commit_group;" ::: "memory")
#define CP_WAIT2()  asm volatile("cp.async.wait_group 2;" ::: "memory")

__device__ __forceinline__ float to_tf32(float x) {
    uint32_t r;
    asm("cvt.rna.tf32.f32 %0, %1;" : "=r"(r) : "f"(x));
    return __uint_as_float(r);
}

#define MMA1688(c, a, b)                                                    \
    asm volatile("mma.sync.aligned.m16n8k8.row.col.f32.tf32.tf32.f32 "      \
        "{%0,%1,%2,%3},{%4,%5,%6,%7},{%8,%9},{%0,%1,%2,%3};"                \
        : "+f"((c)[0]), "+f"((c)[1]), "+f"((c)[2]), "+f"((c)[3])            \
        : "r"((a)[0]), "r"((a)[1]), "r"((a)[2]), "r"((a)[3]),               \
          "r"((b)[0]), "r"((b)[1]))

// ================= TF32 mma.sync GEMM =================
// D[m,n] = sum_k A[m,k]*B[n,k], A/B pre-rounded to tf32.
// CTA 128x128, 8 warps (2x4), warp tile 64x32, BK=32, 3-stage cp.async,
// 2 CTAs/SM (occupancy experiment: 4 warps/SMSP to hide LDS/HMMA latency).
// EPI: 0 = plain store, 1 = store + fused column stats, 2 = atomicAdd (split-K).
constexpr int BK        = 32;
constexpr int STRIDE_W  = 36;                 // fp32 words per smem row (144B, conflict-free)
constexpr int TILE_W    = 128 * STRIDE_W;
constexpr int STAGE_W   = 2 * TILE_W;         // A,B
constexpr int NSTAGE    = 3;
constexpr int GEMM_SMEM = NSTAGE * STAGE_W * 4;   // 110592 B -> 2 CTAs/SM

template<int EPI>
__global__ __launch_bounds__(256, 2)
void k_mma_gemm(const float* __restrict__ A, const float* __restrict__ B,
                float* __restrict__ C, float* __restrict__ stats,
                int lda, int ldb, int ldc, int nChunks) {
    extern __shared__ uint32_t sw[];
    const int tid = threadIdx.x;
    const int wid = tid >> 5, lane = tid & 31;
    const int g = lane >> 2, tig = lane & 3;
    const int wr = wid >> 2, wc = wid & 3;      // warp grid 2 (M) x 4 (N)
    const int nBase = blockIdx.x * 128;
    const int mBase = blockIdx.y * 128;
    const size_t kOff0 = (size_t)blockIdx.z * nChunks * BK;

    float acc[4][4][4];
    #pragma unroll
    for (int i = 0; i < 4; i++)
        #pragma unroll
        for (int j = 0; j < 4; j++)
            #pragma unroll
            for (int v = 0; v < 4; v++) acc[i][j][v] = 0.f;

    const uint32_t sbase = smem_u32(sw);

    auto issue = [&](int c) {
        if (c < nChunks) {
            const uint32_t sb = sbase + (uint32_t)((c % NSTAGE) * STAGE_W) * 4u;
            const size_t kEl = kOff0 + (size_t)c * BK;
            #pragma unroll
            for (int i = 0; i < 8; i++) {
                const int idx = i * 256 + tid;
                const int mat = idx >> 10;            // 0=A, 1=B
                const int within = idx & 1023;
                const int row = within >> 3;
                const int kg = within & 7;
                const float* p = mat ? B : A;
                const size_t ro = mat ? (size_t)(nBase + row) * ldb
                                      : (size_t)(mBase + row) * lda;
                const uint32_t dst = sb + (uint32_t)(mat * TILE_W + row * STRIDE_W + kg * 4) * 4u;
                cp_async16(dst, p + ro + kEl + kg * 4);
            }
        }
        CP_COMMIT();
    };

    issue(0); issue(1); issue(2);

    for (int c = 0; c < nChunks; ++c) {
        CP_WAIT2();
        __syncthreads();
        const uint32_t* sA = sw + (c % NSTAGE) * STAGE_W;
        const uint32_t* sB = sA + TILE_W;

        #pragma unroll
        for (int step = 0; step < 4; ++step) {
            const int kw = step * 8 + tig;
            uint32_t Ar[4][4], Bf[4][2];
            #pragma unroll
            for (int mf = 0; mf < 4; mf++) {
                const int r0 = wr * 64 + mf * 16 + g;
                Ar[mf][0] = sA[ r0      * STRIDE_W + kw];
                Ar[mf][1] = sA[(r0 + 8) * STRIDE_W + kw];
                Ar[mf][2] = sA[ r0      * STRIDE_W + kw + 4];
                Ar[mf][3] = sA[(r0 + 8) * STRIDE_W + kw + 4];
            }
            #pragma unroll
            for (int nf = 0; nf < 4; nf++) {
                const int n0 = wc * 32 + nf * 8 + g;
                Bf[nf][0] = sB[n0 * STRIDE_W + kw];
                Bf[nf][1] = sB[n0 * STRIDE_W + kw + 4];
            }
            #pragma unroll
            for (int mf = 0; mf < 4; mf++)
                #pragma unroll
                for (int nf = 0; nf < 4; nf++)
                    MMA1688(acc[mf][nf], Ar[mf], Bf[nf]);
        }
        __syncthreads();
        issue(c + NSTAGE);
    }

    // ---- epilogue ----
    #pragma unroll
    for (int mf = 0; mf < 4; mf++) {
        const int row = mBase + wr * 64 + mf * 16 + g;
        #pragma unroll
        for (int nf = 0; nf < 4; nf++) {
            const int col = nBase + wc * 32 + nf * 8 + tig * 2;
            float* p0 = &C[(size_t)row * ldc + col];
            float* p1 = &C[(size_t)(row + 8) * ldc + col];
            if (EPI == 2) {
                atomicAdd(p0,     acc[mf][nf][0]);
                atomicAdd(p0 + 1, acc[mf][nf][1]);
                atomicAdd(p1,     acc[mf][nf][2]);
                atomicAdd(p1 + 1, acc[mf][nf][3]);
            } else {
                *(float2*)p0 = make_float2(acc[mf][nf][0], acc[mf][nf][1]);
                *(float2*)p1 = make_float2(acc[mf][nf][2], acc[mf][nf][3]);
            }
        }
    }

    if constexpr (EPI == 1) {   // fused per-column sum / sumsq
        __shared__ float sSum[128], sSq[128];
        if (tid < 128) { sSum[tid] = 0.f; sSq[tid] = 0.f; }
        __syncthreads();
        #pragma unroll
        for (int nf = 0; nf < 4; nf++) {
            #pragma unroll
            for (int b = 0; b < 2; b++) {
                float s = 0.f, q = 0.f;
                #pragma unroll
                for (int mf = 0; mf < 4; mf++) {
                    float v0 = acc[mf][nf][b], v1 = acc[mf][nf][b + 2];
                    s += v0 + v1; q += v0 * v0 + v1 * v1;
                }
                s += __shfl_xor_sync(0xffffffffu, s, 16);
                s += __shfl_xor_sync(0xffffffffu, s, 8);
                s += __shfl_xor_sync(0xffffffffu, s, 4);
                q += __shfl_xor_sync(0xffffffffu, q, 16);
                q += __shfl_xor_sync(0xffffffffu, q, 8);
                q += __shfl_xor_sync(0xffffffffu, q, 4);
                if (g == 0) {
                    const int col = wc * 32 + nf * 8 + tig * 2 + b;
                    atomicAdd(&sSum[col], s);
                    atomicAdd(&sSq[col],  q);
                }
            }
        }
        __syncthreads();
        if (tid < 128) {
            atomicAdd(&stats[nBase + tid],       sSum[tid]);
            atomicAdd(&stats[REP + nBase + tid], sSq[tid]);
        }
    }
}

// ================= glue kernels =================
__global__ void k_zero(float* __restrict__ h6, float* __restrict__ h7,
                       float* __restrict__ stats) {
    int i = blockIdx.x * blockDim.x + threadIdx.x;
    if (i < NBOX * REP) { h6[i] = 0.f; h7[i] = 0.f; }
    if (i < 2 * REP)    stats[i] = 0.f;
}

// ROIAlign -> A [50176, 896] (tf32-rounded), k = c*7 + z
__global__ void k_roi(const float* __restrict__ feat, const float* __restrict__ boxes,
                      const int* __restrict__ bidx, float* __restrict__ A) {
    const int xy = blockIdx.x, n = blockIdx.y, c = threadIdx.x;
    const int qx = xy / RES7, qy = xy % RES7;

    const float x1 = boxes[n*6+0]*PX_SCALE, y1 = boxes[n*6+1]*PX_SCALE,
                z1 = boxes[n*6+2]*PX_SCALE, x2 = boxes[n*6+3]*PX_SCALE,
                y2 = boxes[n*6+4]*PX_SCALE, z2 = boxes[n*6+5]*PX_SCALE;
    const float bx = fmaxf(x2-x1, 1.f) * (1.f/RES7);
    const float by = fmaxf(y2-y1, 1.f) * (1.f/RES7);
    const float bz = fmaxf(z2-z1, 1.f) * (1.f/RES7);
    const float px = x1 + ((float)qx + 0.5f) * bx;
    const float py = y1 + ((float)qy + 0.5f) * by;
    const float fx = floorf(px), lx = px - fx;
    const float fy = floorf(py), ly = py - fy;
    int ix0 = min(max((int)fx, 0), DIMX-1);
    int ix1 = min(max((int)fx + 1, 0), DIMX-1);
    int iy0 = min(max((int)fy, 0), DIMY-1);
    int iy1 = min(max((int)fy + 1, 0), DIMY-1);
    const int b = bidx[n];
    int base[4]; float wxy[4];
    base[0] = ((b*DIMX+ix0)*DIMY+iy0)*DIMZ; wxy[0] = (1.f-lx)*(1.f-ly);
    base[1] = ((b*DIMX+ix0)*DIMY+iy1)*DIMZ; wxy[1] = (1.f-lx)*ly;
    base[2] = ((b*DIMX+ix1)*DIMY+iy0)*DIMZ; wxy[2] = lx*(1.f-ly);
    base[3] = ((b*DIMX+ix1)*DIMY+iy1)*DIMZ; wxy[3] = lx*ly;

    float* Arow = A + (size_t)(n * 49 + xy) * KCONV;
    #pragma unroll
    for (int z = 0; z < RES7; z++) {
        const float pz = z1 + ((float)z + 0.5f) * bz;
        const float fz = floorf(pz), lz = pz - fz;
        int iz0 = min(max((int)fz, 0), DIMZ-1);
        int iz1 = min(max((int)fz + 1, 0), DIMZ-1);
        float v = 0.f;
        #pragma unroll
        for (int q = 0; q < 4; q++) {
            float f0 = feat[(size_t)(base[q] + iz0) * C_IN + c];
            float f1 = feat[(size_t)(base[q] + iz1) * C_IN + c];
            v += wxy[q] * ((1.f - lz) * f0 + lz * f1);
        }
        Arow[c * RES7 + z] = to_tf32(v);
    }
}

// transpose + tf32-round: src [R,NC] -> dst [NC,R]
__global__ void k_tcvt(const float* __restrict__ src, float* __restrict__ dst,
                       int R, int NC) {
    __shared__ float t[32][33];
    const int c = blockIdx.x * 32 + threadIdx.x;
    const int r0 = blockIdx.y * 32;
    for (int j = threadIdx.y; j < 32; j += 8)
        t[j][threadIdx.x] = src[(size_t)(r0 + j) * NC + c];
    __syncthreads();
    for (int j = threadIdx.y; j < 32; j += 8)
        dst[(size_t)(blockIdx.x * 32 + j) * R + r0 + threadIdx.x] = to_tf32(t[threadIdx.x][j]);
}

// elementwise tf32-round (conv_w already [r, k])
__global__ void k_cvt(const float* __restrict__ src, float* __restrict__ dst, int n) {
    int i = blockIdx.x * blockDim.x + threadIdx.x;
    if (i < n) dst[i] = to_tf32(src[i]);
}

__global__ void k_finalize(const float* __restrict__ stats,
                           float* __restrict__ mean, float* __restrict__ rsig) {
    int r = blockIdx.x * blockDim.x + threadIdx.x;
    if (r < REP) {
        const float inv = 1.0f / (float)MROWS;
        float mu = stats[r] * inv;
        float v  = stats[REP + r] * inv - mu * mu;
        mean[r] = mu;
        rsig[r] = rsqrtf(v + 1e-5f);
    }
}

// normalize + relu + transpose -> X2 [n, r*49+xy] (tf32)
__global__ __launch_bounds__(256) void k_norm(
    const float* __restrict__ Y, float* __restrict__ X2,
    const float* __restrict__ mean, const float* __restrict__ rsig,
    const float* __restrict__ gamma, const float* __restrict__ beta) {
    const int n = blockIdx.x;
    __shared__ float tile[49][129];
    __shared__ float sm[128], sr[128], sg[128], sb[128];
    for (int rc = 0; rc < 7; rc++) {
        const int rbase = rc * 128;
        if (threadIdx.x < 128) {
            int r = rbase + threadIdx.x;
            sm[threadIdx.x] = mean[r];  sr[threadIdx.x] = rsig[r];
            sg[threadIdx.x] = gamma[r]; sb[threadIdx.x] = beta[r];
        }
        for (int idx = threadIdx.x; idx < 49 * 128; idx += 256) {
            int xy = idx >> 7, rr = idx & 127;
            tile[xy][rr] = Y[(size_t)(n * 49 + xy) * REP + rbase + rr];
        }
        __syncthreads();
        for (int o = threadIdx.x; o < 128 * 49; o += 256) {
            int rr = o / 49, xy = o % 49;
            float v = (tile[xy][rr] - sm[rr]) * sr[rr] * sg[rr] + sb[rr];
            X2[(size_t)n * INSZ + rbase * 49 + o] = to_tf32(fmaxf(v, 0.f));
        }
        __syncthreads();
    }
}

// bias + relu + tf32-round: H6 -> X3
__global__ void k_bias_relu_cvt(const float* __restrict__ in, const float* __restrict__ bias,
                                float* __restrict__ dst) {
    int i = blockIdx.x * blockDim.x + threadIdx.x;
    if (i < NBOX * REP)
        dst[i] = to_tf32(fmaxf(in[i] + bias[i % REP], 0.f));
}

// bias + relu: H7 -> out
__global__ void k_bias_relu(const float* __restrict__ in, const float* __restrict__ bias,
                            float* __restrict__ out) {
    int i = blockIdx.x * blockDim.x + threadIdx.x;
    if (i < NBOX * REP)
        out[i] = fmaxf(in[i] + bias[i % REP], 0.f);
}

// ---------------- launch ----------------
extern "C" void kernel_launch(void* const* d_in, const int* in_sizes, int n_in,
                              void* d_out, int out_size) {
    const float* feat   = (const float*)d_in[0];
    const float* boxes  = (const float*)d_in[1];
    const float* conv_w = (const float*)d_in[2];
    // conv_b (d_in[3]) cancels in the mean subtraction
    const float* gamma  = (const float*)d_in[4];
    const float* beta   = (const float*)d_in[5];
    const float* fc6_w  = (const float*)d_in[6];
    const float* fc6_b  = (const float*)d_in[7];
    const float* fc7_w  = (const float*)d_in[8];
    const float* fc7_b  = (const float*)d_in[9];
    const int*   bidx   = (const int*)d_in[10];
    float* out = (float*)d_out;

    auto sym = [](const void* s) { void* p = nullptr; cudaGetSymbolAddress(&p, s); return p; };
    float* A    = (float*)sym(g_A);
    float* Y    = (float*)sym(g_Y);
    float* X2   = (float*)sym(g_X2);
    float* WC   = (float*)sym(g_WC);
    float* W6T  = (float*)sym(g_W6T);
    float* W7T  = (float*)sym(g_W7T);
    float* X3   = (float*)sym(g_X3);
    float* H6   = (float*)sym(g_H6);
    float* H7   = (float*)sym(g_H7);
    float* STATS= (float*)sym(g_stats);
    float* MEAN = (float*)sym(g_mean);
    float* RSIG = (float*)sym(g_rsig);

    cudaFuncSetAttribute(k_mma_gemm<1>, cudaFuncAttributeMaxDynamicSharedMemorySize, GEMM_SMEM);
    cudaFuncSetAttribute(k_mma_gemm<2>, cudaFuncAttributeMaxDynamicSharedMemorySize, GEMM_SMEM);

    // 1. zero accumulators + stats
    k_zero<<<3584, 256>>>(H6, H7, STATS);
    // 2. weight conversions (tf32 rounding)
    k_cvt<<<(REP * KCONV + 255) / 256, 256>>>(conv_w, WC, REP * KCONV);
    k_tcvt<<<dim3(REP / 32, INSZ / 32), dim3(32, 8)>>>(fc6_w, W6T, INSZ, REP);
    k_tcvt<<<dim3(REP / 32, REP / 32), dim3(32, 8)>>>(fc7_w, W7T, REP, REP);
    // 3. ROIAlign -> A (tf32)
    k_roi<<<dim3(49, NBOX), 128>>>(feat, boxes, bidx, A);
    // 4. conv einsum GEMM + fused stats: Y = A @ WC^T   (K=896, 28 chunks)
    k_mma_gemm<1><<<dim3(7, 392, 1), 256, GEMM_SMEM>>>(
        A, WC, Y, STATS, KCONV, KCONV, REP, 28);
    // 5. mean / rsig
    k_finalize<<<7, 128>>>(STATS, MEAN, RSIG);
    // 6. normalize + relu + transpose -> X2 (tf32)
    k_norm<<<NBOX, 256>>>(Y, X2, MEAN, RSIG, gamma, beta);
    // 7. fc6 GEMM, split-K 14 (98 chunks each): H6 += X2 @ W6T^T
    k_mma_gemm<2><<<dim3(7, 8, 14), 256, GEMM_SMEM>>>(
        X2, W6T, H6, nullptr, INSZ, INSZ, REP, 98);
    // 8. bias+relu -> X3 (tf32)
    k_bias_relu_cvt<<<3584, 256>>>(H6, fc6_b, X3);
    // 9. fc7 GEMM, split-K 4 (7 chunks each)
    k_mma_gemm<2><<<dim3(7, 8, 4), 256, GEMM_SMEM>>>(
        X3, W7T, H7, nullptr, REP, REP, REP, 7);
    k_bias_relu<<<3584, 256>>>(H7, fc7_b, out);
}

// round 6
// speedup vs baseline: 3.3803x; 1.1088x over previous
#include <cuda_runtime.h>
#include <cstdint>
#include <cstddef>

// ---------------- problem constants ----------------
constexpr int RES7  = 7;
constexpr int NBOX  = 1024;
constexpr int C_IN  = 128;
constexpr int REP   = 896;                  // 128*7
constexpr int MROWS = NBOX * 49;            // 50176
constexpr int KCONV = 896;                  // C_IN*7
constexpr int INSZ  = 43904;                // REP*49
constexpr int DIMX = 80, DIMY = 80, DIMZ = 20;
constexpr float PX_SCALE = 5.0f;            // 20 * 0.25

// ---------------- static scratch (fragment-order packed GEMM operands) ------
__device__ float g_A  [(size_t)MROWS * KCONV];   // roi out, packed A
__device__ float g_Y  [(size_t)MROWS * REP];     // conv out (row-major)
__device__ float g_X2 [(size_t)NBOX * INSZ];     // normalized, packed A
__device__ float g_WC [(size_t)REP * KCONV];     // conv_w, packed B
__device__ float g_W6 [(size_t)REP * INSZ];      // fc6_w, packed B
__device__ float g_W7 [(size_t)REP * REP];       // fc7_w, packed B
__device__ float g_X3 [(size_t)NBOX * REP];      // relu(fc6), packed A
__device__ float g_H6 [(size_t)NBOX * REP];
__device__ float g_H7 [(size_t)NBOX * REP];
__device__ float g_stats[2 * REP];
__device__ float g_mean[REP];
__device__ float g_rsig[REP];

// ---------------- helpers ----------------
__device__ __forceinline__ uint32_t smem_u32(const void* p) {
    uint32_t a;
    asm("{ .reg .u64 t; cvta.to.shared.u64 t, %1; cvt.u32.u64 %0, t; }" : "=r"(a) : "l"(p));
    return a;
}
__device__ __forceinline__ void cp_async16(uint32_t dst, const void* src) {
    asm volatile("cp.async.cg.shared.global [%0], [%1], 16;" :: "r"(dst), "l"(src) : "memory");
}
#define CP_COMMIT() asm volatile("cp.async.commit_group;" ::: "memory")
#define CP_WAIT2()  asm volatile("cp.async.wait_group 2;" ::: "memory")

__device__ __forceinline__ float to_tf32(float x) {
    uint32_t r;
    asm("cvt.rna.tf32.f32 %0, %1;" : "=r"(r) : "f"(x));
    return __uint_as_float(r);
}

#define MMA1688(c, a, b)                                                    \
    asm volatile("mma.sync.aligned.m16n8k8.row.col.f32.tf32.tf32.f32 "      \
        "{%0,%1,%2,%3},{%4,%5,%6,%7},{%8,%9},{%0,%1,%2,%3};"                \
        : "+f"((c)[0]), "+f"((c)[1]), "+f"((c)[2]), "+f"((c)[3])            \
        : "r"((a)[0]), "r"((a)[1]), "r"((a)[2]), "r"((a)[3]),               \
          "r"((b)[0]), "r"((b)[1]))

#define LDS128(r0_, r1_, r2_, r3_, addr)                                    \
    asm volatile("ld.shared.v4.b32 {%0,%1,%2,%3}, [%4];"                    \
        : "=r"(r0_), "=r"(r1_), "=r"(r2_), "=r"(r3_) : "r"(addr))

// ---------------- fragment-order packing ----------------
// A: per 128-row x 32-k block (16KB): thread(lane) of warp-row wr, frag (mf,step)
//    holds words (r0,kw),(r0+8,kw),(r0,kw+4),(r0+8,kw+4) contiguous.
__device__ __forceinline__ size_t a_pack_idx(int m, int k, int nKC) {
    const int mBlk = m >> 7, mr = m & 127;
    const int wr = mr >> 6, mf = (mr >> 4) & 3, h = (mr >> 3) & 1, g = mr & 7;
    const int kc = k >> 5, kk = k & 31;
    const int step = kk >> 3, r = kk & 7, tig = r & 3, q = r >> 2;
    const int unit = ((((step * 4 + mf) * 2 + wr) * 8 + g) * 4 + tig);
    return (((size_t)mBlk * nKC + kc) << 12) + (unit << 2) + (q * 2 + h);
}
// B: per 128-col x 32-k block: thread holds (n0,kw),(n0,kw+4) for an nf pair.
__device__ __forceinline__ size_t b_pack_idx(int n, int k, int nKC) {
    const int nBlk = n >> 7, nr = n & 127;
    const int wc = nr >> 5, nf = (nr >> 3) & 3, g = nr & 7;
    const int np = nf >> 1, pf = nf & 1;
    const int kc = k >> 5, kk = k & 31;
    const int step = kk >> 3, r = kk & 7, tig = r & 3, q = r >> 2;
    const int unit = ((((step * 2 + np) * 4 + wc) * 8 + g) * 4 + tig);
    return (((size_t)nBlk * nKC + kc) << 12) + (unit << 2) + (pf * 2 + q);
}

// ================= TF32 mma.sync GEMM (packed operands) =================
// CTA 128x128, 8 warps (2x4), warp tile 64x32, BK=32, 3-stage, 2 CTAs/SM.
// EPI: 1 = store + fused column stats, 2 = atomicAdd (split-K).
constexpr int NSTAGE    = 3;
constexpr int STAGE_B   = 32768;                  // A 16KB + B 16KB
constexpr int GEMM_SMEM = NSTAGE * STAGE_B;       // 98304 B -> 2 CTAs/SM

template<int EPI>
__global__ __launch_bounds__(256, 2)
void k_mma_gemm(const float* __restrict__ A, const float* __restrict__ B,
                float* __restrict__ C, float* __restrict__ stats,
                int nKC, int ldc, int nChunks) {
    extern __shared__ uint32_t sw[];
    const int tid = threadIdx.x;
    const int wid = tid >> 5, lane = tid & 31;
    const int g = lane >> 2, tig = lane & 3;
    const int wr = wid >> 2, wc = wid & 3;
    const int nBase = blockIdx.x * 128;
    const int mBase = blockIdx.y * 128;
    const int chunk0 = blockIdx.z * nChunks;

    float acc[4][4][4];
    #pragma unroll
    for (int i = 0; i < 4; i++)
        #pragma unroll
        for (int j = 0; j < 4; j++)
            #pragma unroll
            for (int v = 0; v < 4; v++) acc[i][j][v] = 0.f;

    const uint32_t sbase = smem_u32(sw);
    const float* Abase = A + (((size_t)(mBase >> 7) * nKC + chunk0) << 12);
    const float* Bbase = B + (((size_t)(nBase >> 7) * nKC + chunk0) << 12);

    auto issue = [&](int c) {
        if (c < nChunks) {
            const float* Ab = Abase + ((size_t)c << 12);
            const float* Bb = Bbase + ((size_t)c << 12);
            const uint32_t sb = sbase + (c % NSTAGE) * STAGE_B;
            #pragma unroll
            for (int i = 0; i < 8; i++) {
                const int idx = i * 256 + tid;          // 0..2047 16B-units
                const int mat = idx >> 10;
                const int unit = idx & 1023;
                const float* src = (mat ? Bb : Ab) + (unit << 2);
                cp_async16(sb + mat * 16384 + (unit << 4), src);
            }
        }
        CP_COMMIT();
    };

    issue(0); issue(1); issue(2);

    for (int c = 0; c < nChunks; ++c) {
        CP_WAIT2();
        __syncthreads();
        const uint32_t sA = sbase + (c % NSTAGE) * STAGE_B;
        const uint32_t sB = sA + 16384;

        #pragma unroll
        for (int step = 0; step < 4; ++step) {
            uint32_t Ar[4][4];
            uint32_t Bw[2][4];
            #pragma unroll
            for (int mf = 0; mf < 4; mf++) {
                const uint32_t addr = sA + (((((step * 4 + mf) * 2 + wr) * 32) + lane) << 4);
                LDS128(Ar[mf][0], Ar[mf][1], Ar[mf][2], Ar[mf][3], addr);
            }
            #pragma unroll
            for (int np = 0; np < 2; np++) {
                const uint32_t addr = sB + (((((step * 2 + np) * 4 + wc) * 32) + lane) << 4);
                LDS128(Bw[np][0], Bw[np][1], Bw[np][2], Bw[np][3], addr);
            }
            #pragma unroll
            for (int mf = 0; mf < 4; mf++) {
                #pragma unroll
                for (int nf = 0; nf < 4; nf++) {
                    uint32_t bfrag[2];
                    bfrag[0] = Bw[nf >> 1][(nf & 1) * 2 + 0];
                    bfrag[1] = Bw[nf >> 1][(nf & 1) * 2 + 1];
                    MMA1688(acc[mf][nf], Ar[mf], bfrag);
                }
            }
        }
        __syncthreads();
        issue(c + NSTAGE);
    }

    // ---- epilogue ----
    #pragma unroll
    for (int mf = 0; mf < 4; mf++) {
        const int row = mBase + wr * 64 + mf * 16 + g;
        #pragma unroll
        for (int nf = 0; nf < 4; nf++) {
            const int col = nBase + wc * 32 + nf * 8 + tig * 2;
            float* p0 = &C[(size_t)row * ldc + col];
            float* p1 = &C[(size_t)(row + 8) * ldc + col];
            if (EPI == 2) {
                atomicAdd(p0,     acc[mf][nf][0]);
                atomicAdd(p0 + 1, acc[mf][nf][1]);
                atomicAdd(p1,     acc[mf][nf][2]);
                atomicAdd(p1 + 1, acc[mf][nf][3]);
            } else {
                *(float2*)p0 = make_float2(acc[mf][nf][0], acc[mf][nf][1]);
                *(float2*)p1 = make_float2(acc[mf][nf][2], acc[mf][nf][3]);
            }
        }
    }

    if constexpr (EPI == 1) {   // fused per-column sum / sumsq
        __shared__ float sSum[128], sSq[128];
        if (tid < 128) { sSum[tid] = 0.f; sSq[tid] = 0.f; }
        __syncthreads();
        #pragma unroll
        for (int nf = 0; nf < 4; nf++) {
            #pragma unroll
            for (int b = 0; b < 2; b++) {
                float s = 0.f, q = 0.f;
                #pragma unroll
                for (int mf = 0; mf < 4; mf++) {
                    float v0 = acc[mf][nf][b], v1 = acc[mf][nf][b + 2];
                    s += v0 + v1; q += v0 * v0 + v1 * v1;
                }
                s += __shfl_xor_sync(0xffffffffu, s, 16);
                s += __shfl_xor_sync(0xffffffffu, s, 8);
                s += __shfl_xor_sync(0xffffffffu, s, 4);
                q += __shfl_xor_sync(0xffffffffu, q, 16);
                q += __shfl_xor_sync(0xffffffffu, q, 8);
                q += __shfl_xor_sync(0xffffffffu, q, 4);
                if (g == 0) {
                    const int col = wc * 32 + nf * 8 + tig * 2 + b;
                    atomicAdd(&sSum[col], s);
                    atomicAdd(&sSq[col],  q);
                }
            }
        }
        __syncthreads();
        if (tid < 128) {
            atomicAdd(&stats[nBase + tid],       sSum[tid]);
            atomicAdd(&stats[REP + nBase + tid], sSq[tid]);
        }
    }
}

// ================= glue kernels =================
__global__ void k_zero(float* __restrict__ h6, float* __restrict__ h7,
                       float* __restrict__ stats) {
    int i = blockIdx.x * blockDim.x + threadIdx.x;
    if (i < NBOX * REP) { h6[i] = 0.f; h7[i] = 0.f; }
    if (i < 2 * REP)    stats[i] = 0.f;
}

// ROIAlign -> packed A [50176, 896], k = c*7 + z, nKC = 28
__global__ void k_roi(const float* __restrict__ feat, const float* __restrict__ boxes,
                      const int* __restrict__ bidx, float* __restrict__ A) {
    const int xy = blockIdx.x, n = blockIdx.y, c = threadIdx.x;
    const int qx = xy / RES7, qy = xy % RES7;
    const int m = n * 49 + xy;

    const float x1 = boxes[n*6+0]*PX_SCALE, y1 = boxes[n*6+1]*PX_SCALE,
                z1 = boxes[n*6+2]*PX_SCALE, x2 = boxes[n*6+3]*PX_SCALE,
                y2 = boxes[n*6+4]*PX_SCALE, z2 = boxes[n*6+5]*PX_SCALE;
    const float bx = fmaxf(x2-x1, 1.f) * (1.f/RES7);
    const float by = fmaxf(y2-y1, 1.f) * (1.f/RES7);
    const float bz = fmaxf(z2-z1, 1.f) * (1.f/RES7);
    const float px = x1 + ((float)qx + 0.5f) * bx;
    const float py = y1 + ((float)qy + 0.5f) * by;
    const float fx = floorf(px), lx = px - fx;
    const float fy = floorf(py), ly = py - fy;
    int ix0 = min(max((int)fx, 0), DIMX-1);
    int ix1 = min(max((int)fx + 1, 0), DIMX-1);
    int iy0 = min(max((int)fy, 0), DIMY-1);
    int iy1 = min(max((int)fy + 1, 0), DIMY-1);
    const int b = bidx[n];
    int base[4]; float wxy[4];
    base[0] = ((b*DIMX+ix0)*DIMY+iy0)*DIMZ; wxy[0] = (1.f-lx)*(1.f-ly);
    base[1] = ((b*DIMX+ix0)*DIMY+iy1)*DIMZ; wxy[1] = (1.f-lx)*ly;
    base[2] = ((b*DIMX+ix1)*DIMY+iy0)*DIMZ; wxy[2] = lx*(1.f-ly);
    base[3] = ((b*DIMX+ix1)*DIMY+iy1)*DIMZ; wxy[3] = lx*ly;

    #pragma unroll
    for (int z = 0; z < RES7; z++) {
        const float pz = z1 + ((float)z + 0.5f) * bz;
        const float fz = floorf(pz), lz = pz - fz;
        int iz0 = min(max((int)fz, 0), DIMZ-1);
        int iz1 = min(max((int)fz + 1, 0), DIMZ-1);
        float v = 0.f;
        #pragma unroll
        for (int q = 0; q < 4; q++) {
            float f0 = feat[(size_t)(base[q] + iz0) * C_IN + c];
            float f1 = feat[(size_t)(base[q] + iz1) * C_IN + c];
            v += wxy[q] * ((1.f - lz) * f0 + lz * f1);
        }
        A[a_pack_idx(m, c * RES7 + z, 28)] = to_tf32(v);
    }
}

// transpose + tf32 + pack B: src [K_total rows, 896 cols] -> packed B(n=col, k=row)
__global__ void k_tcvt(const float* __restrict__ src, float* __restrict__ dst, int nKC) {
    __shared__ float t[32][33];
    const int c = blockIdx.x * 32 + threadIdx.x;      // n (col)
    const int r0 = blockIdx.y * 32;                   // k (row)
    for (int j = threadIdx.y; j < 32; j += 8)
        t[j][threadIdx.x] = src[(size_t)(r0 + j) * REP + c];
    __syncthreads();
    for (int j = threadIdx.y; j < 32; j += 8) {
        const int n = blockIdx.x * 32 + j;
        const int k = r0 + threadIdx.x;
        dst[b_pack_idx(n, k, nKC)] = to_tf32(t[threadIdx.x][j]);
    }
}

// tf32 + pack B (conv_w already [n=r, k])
__global__ void k_cvt(const float* __restrict__ src, float* __restrict__ dst, int total) {
    int i = blockIdx.x * blockDim.x + threadIdx.x;
    if (i < total) {
        const int n = i / KCONV, k = i % KCONV;
        dst[b_pack_idx(n, k, 28)] = to_tf32(src[i]);
    }
}

__global__ void k_finalize(const float* __restrict__ stats,
                           float* __restrict__ mean, float* __restrict__ rsig) {
    int r = blockIdx.x * blockDim.x + threadIdx.x;
    if (r < REP) {
        const float inv = 1.0f / (float)MROWS;
        float mu = stats[r] * inv;
        float v  = stats[REP + r] * inv - mu * mu;
        mean[r] = mu;
        rsig[r] = rsqrtf(v + 1e-5f);
    }
}

// normalize + relu + pack A: Y[n*49+xy, r] -> X2 packed(m=n, k=r*49+xy), nKC=1372
__global__ __launch_bounds__(256) void k_norm(
    const float* __restrict__ Y, float* __restrict__ X2,
    const float* __restrict__ mean, const float* __restrict__ rsig,
    const float* __restrict__ gamma, const float* __restrict__ beta) {
    const int n = blockIdx.x;
    __shared__ float tile[49][129];
    __shared__ float sm[128], sr[128], sg[128], sb[128];
    for (int rc = 0; rc < 7; rc++) {
        const int rbase = rc * 128;
        if (threadIdx.x < 128) {
            int r = rbase + threadIdx.x;
            sm[threadIdx.x] = mean[r];  sr[threadIdx.x] = rsig[r];
            sg[threadIdx.x] = gamma[r]; sb[threadIdx.x] = beta[r];
        }
        for (int idx = threadIdx.x; idx < 49 * 128; idx += 256) {
            int xy = idx >> 7, rr = idx & 127;
            tile[xy][rr] = Y[(size_t)(n * 49 + xy) * REP + rbase + rr];
        }
        __syncthreads();
        for (int o = threadIdx.x; o < 128 * 49; o += 256) {
            int rr = o / 49, xy = o % 49;
            float v = (tile[xy][rr] - sm[rr]) * sr[rr] * sg[rr] + sb[rr];
            X2[a_pack_idx(n, rbase * 49 + o, 1372)] = to_tf32(fmaxf(v, 0.f));
        }
        __syncthreads();
    }
}

// bias + relu + pack A: H6 -> X3 packed, nKC=28
__global__ void k_bias_relu_cvt(const float* __restrict__ in, const float* __restrict__ bias,
                                float* __restrict__ dst) {
    int i = blockIdx.x * blockDim.x + threadIdx.x;
    if (i < NBOX * REP) {
        const int m = i / REP, k = i % REP;
        dst[a_pack_idx(m, k, 28)] = to_tf32(fmaxf(in[i] + bias[k], 0.f));
    }
}

// bias + relu: H7 -> out
__global__ void k_bias_relu(const float* __restrict__ in, const float* __restrict__ bias,
                            float* __restrict__ out) {
    int i = blockIdx.x * blockDim.x + threadIdx.x;
    if (i < NBOX * REP)
        out[i] = fmaxf(in[i] + bias[i % REP], 0.f);
}

// ---------------- launch ----------------
extern "C" void kernel_launch(void* const* d_in, const int* in_sizes, int n_in,
                              void* d_out, int out_size) {
    const float* feat   = (const float*)d_in[0];
    const float* boxes  = (const float*)d_in[1];
    const float* conv_w = (const float*)d_in[2];
    // conv_b (d_in[3]) cancels in the mean subtraction
    const float* gamma  = (const float*)d_in[4];
    const float* beta   = (const float*)d_in[5];
    const float* fc6_w  = (const float*)d_in[6];
    const float* fc6_b  = (const float*)d_in[7];
    const float* fc7_w  = (const float*)d_in[8];
    const float* fc7_b  = (const float*)d_in[9];
    const int*   bidx   = (const int*)d_in[10];
    float* out = (float*)d_out;

    auto sym = [](const void* s) { void* p = nullptr; cudaGetSymbolAddress(&p, s); return p; };
    float* A    = (float*)sym(g_A);
    float* Y    = (float*)sym(g_Y);
    float* X2   = (float*)sym(g_X2);
    float* WC   = (float*)sym(g_WC);
    float* W6   = (float*)sym(g_W6);
    float* W7   = (float*)sym(g_W7);
    float* X3   = (float*)sym(g_X3);
    float* H6   = (float*)sym(g_H6);
    float* H7   = (float*)sym(g_H7);
    float* STATS= (float*)sym(g_stats);
    float* MEAN = (float*)sym(g_mean);
    float* RSIG = (float*)sym(g_rsig);

    cudaFuncSetAttribute(k_mma_gemm<1>, cudaFuncAttributeMaxDynamicSharedMemorySize, GEMM_SMEM);
    cudaFuncSetAttribute(k_mma_gemm<2>, cudaFuncAttributeMaxDynamicSharedMemorySize, GEMM_SMEM);

    // 1. zero accumulators + stats
    k_zero<<<3584, 256>>>(H6, H7, STATS);
    // 2. weight conversions (tf32 + fragment packing)
    k_cvt<<<(REP * KCONV + 255) / 256, 256>>>(conv_w, WC, REP * KCONV);
    k_tcvt<<<dim3(REP / 32, INSZ / 32), dim3(32, 8)>>>(fc6_w, W6, 1372);
    k_tcvt<<<dim3(REP / 32, REP / 32), dim3(32, 8)>>>(fc7_w, W7, 28);
    // 3. ROIAlign -> packed A
    k_roi<<<dim3(49, NBOX), 128>>>(feat, boxes, bidx, A);
    // 4. conv einsum GEMM + fused stats: Y = A @ WC^T   (nKC=28)
    k_mma_gemm<1><<<dim3(7, 392, 1), 256, GEMM_SMEM>>>(
        A, WC, Y, STATS, 28, REP, 28);
    // 5. mean / rsig
    k_finalize<<<7, 128>>>(STATS, MEAN, RSIG);
    // 6. normalize + relu -> X2 packed
    k_norm<<<NBOX, 256>>>(Y, X2, MEAN, RSIG, gamma, beta);
    // 7. fc6 GEMM, split-K 14 (98 chunks each, nKC=1372)
    k_mma_gemm<2><<<dim3(7, 8, 14), 256, GEMM_SMEM>>>(
        X2, W6, H6, nullptr, 1372, REP, 98);
    // 8. bias+relu -> X3 packed
    k_bias_relu_cvt<<<3584, 256>>>(H6, fc6_b, X3);
    // 9. fc7 GEMM, split-K 4 (7 chunks each, nKC=28)
    k_mma_gemm<2><<<dim3(7, 8, 4), 256, GEMM_SMEM>>>(
        X3, W7, H7, nullptr, 28, REP, 7);
    k_bias_relu<<<3584, 256>>>(H7, fc7_b, out);
}